// round 17
// baseline (speedup 1.0000x reference)
#include <cuda_runtime.h>
#include <cuda_bf16.h>
#include <math.h>
#include <cstdint>

#define SEQ 4096
#define DM 1024
#define NH 16
#define HD 64
#define WIN 512

// Scratch (allocation-free rule: __device__ globals)
__device__ float g_qkv[SEQ * 3 * DM];
__device__ float g_cos[SEQ * 32];
__device__ float g_sin[SEQ * 32];
// split-bf16 operands
__device__ __nv_bfloat16 g_xh[SEQ * DM],      g_xl[SEQ * DM];
__device__ __nv_bfloat16 g_wqh[3 * DM * DM],  g_wql[3 * DM * DM];
__device__ __nv_bfloat16 g_woh[DM * DM],      g_wol[DM * DM];
__device__ __nv_bfloat16 g_atth[SEQ * DM],    g_attl[SEQ * DM];
// split-bf16 Q/K/V, head-major [h][l][64]; Q prescaled by 1/8
__device__ __nv_bfloat16 g_qh[NH * SEQ * HD], g_ql[NH * SEQ * HD];
__device__ __nv_bfloat16 g_kh[NH * SEQ * HD], g_kl[NH * SEQ * HD];
__device__ __nv_bfloat16 g_vh[NH * SEQ * HD], g_vl[NH * SEQ * HD];

#define MMA16816(d, a, b)                                              \
    asm volatile(                                                      \
        "mma.sync.aligned.m16n8k16.row.col.f32.bf16.bf16.f32 "         \
        "{%0,%1,%2,%3}, {%4,%5,%6,%7}, {%8,%9}, {%0,%1,%2,%3};"        \
        : "+f"(d[0]), "+f"(d[1]), "+f"(d[2]), "+f"(d[3])               \
        : "r"(a[0]), "r"(a[1]), "r"(a[2]), "r"(a[3]),                  \
          "r"(b[0]), "r"(b[1]))

__device__ __forceinline__ uint32_t smem_u32(const void* p) {
    uint32_t a;
    asm("{ .reg .u64 t; cvta.to.shared.u64 t, %1; cvt.u32.u64 %0, t; }" : "=r"(a) : "l"(p));
    return a;
}
__device__ __forceinline__ void cp_async16(uint32_t saddr, const void* g) {
    asm volatile("cp.async.cg.shared.global [%0], [%1], 16;" :: "r"(saddr), "l"(g));
}
#define CP_COMMIT() asm volatile("cp.async.commit_group;")
#define CP_WAIT0()  asm volatile("cp.async.wait_group 0;")
#define CP_WAIT1()  asm volatile("cp.async.wait_group 1;")

__device__ __forceinline__ void split_store(__nv_bfloat16* ph, __nv_bfloat16* pl,
                                            size_t idx, float a, float b)
{
    __nv_bfloat16 h0 = __float2bfloat16(a);
    __nv_bfloat16 h1 = __float2bfloat16(b);
    __nv_bfloat162 hh; hh.x = h0; hh.y = h1;
    __nv_bfloat162 ll;
    ll.x = __float2bfloat16(a - __bfloat162float(h0));
    ll.y = __float2bfloat16(b - __bfloat162float(h1));
    *(__nv_bfloat162*)&ph[idx] = hh;
    *(__nv_bfloat162*)&pl[idx] = ll;
}

// ===========================================================================
// Pre-split kernels
// ===========================================================================
__global__ __launch_bounds__(256) void split_x_kernel(const float* __restrict__ x)
{
    int idx = blockIdx.x * blockDim.x + threadIdx.x;
    if (idx >= SEQ * DM / 2) return;
    float2 v = ((const float2*)x)[idx];
    split_store(g_xh, g_xl, (size_t)idx * 2, v.x, v.y);
}

__global__ __launch_bounds__(256) void tsplit_kernel(
    const float* __restrict__ W, __nv_bfloat16* __restrict__ Th,
    __nv_bfloat16* __restrict__ Tl, int K, int N)
{
    __shared__ float tile[32][33];
    const int n0 = blockIdx.x * 32;
    const int k0 = blockIdx.y * 32;
    const int tx = threadIdx.x, ty = threadIdx.y;
#pragma unroll
    for (int i = 0; i < 4; i++)
        tile[ty + i * 8][tx] = W[(size_t)(k0 + ty + i * 8) * N + n0 + tx];
    __syncthreads();
#pragma unroll
    for (int i = 0; i < 4; i++) {
        int n = n0 + ty + i * 8;
        int k = k0 + tx;
        float v = tile[tx][ty + i * 8];
        __nv_bfloat16 h = __float2bfloat16(v);
        Th[(size_t)n * K + k] = h;
        Tl[(size_t)n * K + k] = __float2bfloat16(v - __bfloat162float(h));
    }
}

// ===========================================================================
// Double-buffered bf16 HMMA GEMM, 128x64 tile, 256 thr (8 warps, 4m x 2n),
// BK=32, cp.async 2-stage. ~90 regs -> 2 CTAs/SM (16 warps) for latency hiding.
// ===========================================================================
#define GPITCH 40
#define A_ELEMS (128 * GPITCH)
#define B_ELEMS (64 * GPITCH)
#define STAGE_ELEMS (2 * A_ELEMS + 2 * B_ELEMS)
#define GEMM_SMEM (2 * STAGE_ELEMS * 2)     // 61440 bytes

__global__ __launch_bounds__(256, 2) void gemm_bf16_kernel(
    const __nv_bfloat16* __restrict__ Ahg, const __nv_bfloat16* __restrict__ Alg,
    const __nv_bfloat16* __restrict__ Bhg, const __nv_bfloat16* __restrict__ Blg,
    float* __restrict__ C, int M, int N, int K)
{
    extern __shared__ __nv_bfloat16 sm[];
    const uint32_t sb = smem_u32(sm);

    const int tid  = threadIdx.x;
    const int lane = tid & 31;
    const int w    = tid >> 5;
    const int g    = lane >> 2;
    const int tg   = lane & 3;
    const int wm   = w & 3;          // 4 m-warps x 32 rows
    const int wn   = w >> 2;         // 2 n-warps x 32 cols
    const int m0   = blockIdx.y * 128;
    const int n0   = blockIdx.x * 64;

    float acc[2][4][4];
#pragma unroll
    for (int mt = 0; mt < 2; mt++)
#pragma unroll
        for (int nt = 0; nt < 4; nt++)
#pragma unroll
            for (int r = 0; r < 4; r++) acc[mt][nt][r] = 0.f;

    const int l_row = tid >> 2;          // 0..63
    const int l_c8  = (tid & 3) * 8;     // halfword col chunk
#define LOAD_STAGE(st, kt)                                                          \
    do {                                                                            \
        uint32_t base = sb + (uint32_t)(st) * STAGE_ELEMS * 2;                      \
        _Pragma("unroll")                                                           \
        for (int r = 0; r < 2; r++) {                                               \
            int row = l_row + r * 64;                                               \
            uint32_t doff = (uint32_t)(row * GPITCH + l_c8) * 2;                    \
            size_t ao = (size_t)(m0 + row) * K + (kt) + l_c8;                       \
            cp_async16(base + doff,               Ahg + ao);                        \
            cp_async16(base + A_ELEMS * 2 + doff, Alg + ao);                        \
        }                                                                           \
        {                                                                           \
            uint32_t doff = (uint32_t)(l_row * GPITCH + l_c8) * 2;                  \
            size_t bo = (size_t)(n0 + l_row) * K + (kt) + l_c8;                     \
            cp_async16(base + 4 * A_ELEMS + doff,                 Bhg + bo);        \
            cp_async16(base + 4 * A_ELEMS + B_ELEMS * 2 + doff,   Blg + bo);        \
        }                                                                           \
    } while (0)

    const int nch = K >> 5;
    LOAD_STAGE(0, 0);
    CP_COMMIT();

    for (int ch = 0; ch < nch; ch++) {
        if (ch + 1 < nch) {
            LOAD_STAGE((ch + 1) & 1, (ch + 1) * 32);
            CP_COMMIT();
            CP_WAIT1();
        } else {
            CP_WAIT0();
        }
        __syncthreads();

        const __nv_bfloat16* sAh = sm + (ch & 1) * STAGE_ELEMS;
        const __nv_bfloat16* sAl = sAh + A_ELEMS;
        const __nv_bfloat16* sBh = sAl + A_ELEMS;
        const __nv_bfloat16* sBl = sBh + B_ELEMS;

#pragma unroll
        for (int ks = 0; ks < 2; ks++) {
            const int kk = ks * 16 + tg * 2;
            uint32_t bh[4][2], bl[4][2];
#pragma unroll
            for (int nt = 0; nt < 4; nt++) {
                int nn = wn * 32 + nt * 8 + g;
                bh[nt][0] = *(const uint32_t*)&sBh[nn * GPITCH + kk];
                bh[nt][1] = *(const uint32_t*)&sBh[nn * GPITCH + kk + 8];
                bl[nt][0] = *(const uint32_t*)&sBl[nn * GPITCH + kk];
                bl[nt][1] = *(const uint32_t*)&sBl[nn * GPITCH + kk + 8];
            }
#pragma unroll
            for (int mt = 0; mt < 2; mt++) {
                const int rb = wm * 32 + mt * 16;
                uint32_t ah[4], al[4];
                ah[0] = *(const uint32_t*)&sAh[(rb + g)     * GPITCH + kk];
                ah[1] = *(const uint32_t*)&sAh[(rb + g + 8) * GPITCH + kk];
                ah[2] = *(const uint32_t*)&sAh[(rb + g)     * GPITCH + kk + 8];
                ah[3] = *(const uint32_t*)&sAh[(rb + g + 8) * GPITCH + kk + 8];
                al[0] = *(const uint32_t*)&sAl[(rb + g)     * GPITCH + kk];
                al[1] = *(const uint32_t*)&sAl[(rb + g + 8) * GPITCH + kk];
                al[2] = *(const uint32_t*)&sAl[(rb + g)     * GPITCH + kk + 8];
                al[3] = *(const uint32_t*)&sAl[(rb + g + 8) * GPITCH + kk + 8];
#pragma unroll
                for (int nt = 0; nt < 4; nt++) {
                    MMA16816(acc[mt][nt], ah, bh[nt]);
                    MMA16816(acc[mt][nt], ah, bl[nt]);
                    MMA16816(acc[mt][nt], al, bh[nt]);
                }
            }
        }
        __syncthreads();
    }

#pragma unroll
    for (int mt = 0; mt < 2; mt++) {
        const int row = m0 + wm * 32 + mt * 16 + g;
#pragma unroll
        for (int nt = 0; nt < 4; nt++) {
            const int col = n0 + wn * 32 + nt * 8 + tg * 2;
            *(float2*)(C + (size_t)row * N + col) =
                make_float2(acc[mt][nt][0], acc[mt][nt][1]);
            *(float2*)(C + (size_t)(row + 8) * N + col) =
                make_float2(acc[mt][nt][2], acc[mt][nt][3]);
        }
    }
}

// ---------------------------------------------------------------------------
// RoPE tables
// ---------------------------------------------------------------------------
__global__ __launch_bounds__(256) void rope_table_kernel()
{
    int idx = blockIdx.x * blockDim.x + threadIdx.x;
    if (idx >= SEQ * 32) return;
    int p = idx & 31;
    int l = idx >> 5;
    float inv_freq = powf(10000.0f, -(2.0f * (float)p) / 64.0f);
    float ang = (float)l * inv_freq;
    float s, c;
    sincosf(ang, &s, &c);
    g_cos[idx] = c;
    g_sin[idx] = s;
}

// ---------------------------------------------------------------------------
// RoPE + scatter -> split bf16 hi/lo. Q prescaled by 1/8.
// ---------------------------------------------------------------------------
__global__ __launch_bounds__(256) void rope_scatter_kernel(const float* __restrict__ qkv)
{
    int idx = blockIdx.x * blockDim.x + threadIdx.x;
    if (idx >= SEQ * NH * 32) return;
    int p = idx & 31;
    int h = (idx >> 5) & (NH - 1);
    int l = idx >> 9;

    float c = g_cos[l * 32 + p];
    float s = g_sin[l * 32 + p];

    const float* src = qkv + (size_t)l * (3 * DM);
    int col = h * HD + 2 * p;
    float q0 = src[col],          q1 = src[col + 1];
    float k0 = src[DM + col],     k1 = src[DM + col + 1];
    float v0 = src[2 * DM + col], v1 = src[2 * DM + col + 1];

    float qr0 = (q0 * c - q1 * s) * 0.125f;
    float qr1 = (q1 * c + q0 * s) * 0.125f;
    float kr0 = k0 * c - k1 * s;
    float kr1 = k1 * c + k0 * s;

    size_t dst = (size_t)(h * SEQ + l) * HD + 2 * p;
    split_store(g_qh, g_ql, dst, qr0, qr1);
    split_store(g_kh, g_kl, dst, kr0, kr1);
    split_store(g_vh, g_vl, dst, v0, v1);
}

// ---------------------------------------------------------------------------
// HMMA flash attention. Epilogue writes split-bf16 att.
// ---------------------------------------------------------------------------
#define PITCH 72

__global__ __launch_bounds__(128, 3) void attn_mma_kernel(
    const __nv_bfloat16* __restrict__ Qh, const __nv_bfloat16* __restrict__ Ql,
    const __nv_bfloat16* __restrict__ Kh, const __nv_bfloat16* __restrict__ Kl,
    const __nv_bfloat16* __restrict__ Vh, const __nv_bfloat16* __restrict__ Vl,
    __nv_bfloat16* __restrict__ Oh, __nv_bfloat16* __restrict__ Ol)
{
    __shared__ __nv_bfloat16 sKh[64 * PITCH];
    __shared__ __nv_bfloat16 sKl[64 * PITCH];
    __shared__ __nv_bfloat16 sVh[64 * PITCH];
    __shared__ __nv_bfloat16 sVl[64 * PITCH];

    const int tid  = threadIdx.x;
    const int lane = tid & 31;
    const int w    = tid >> 5;
    const int g    = lane >> 2;
    const int tg   = lane & 3;
    const int h    = blockIdx.y;
    const int r0   = blockIdx.x * 64;
    const int qrow = r0 + w * 16 + g;

    uint32_t qfh[4][4], qfl[4][4];
    {
        const size_t base = (size_t)(h * SEQ + qrow) * HD;
#pragma unroll
        for (int kc = 0; kc < 4; kc++) {
            int k0 = kc * 16 + tg * 2;
            qfh[kc][0] = *(const uint32_t*)&Qh[base + k0];
            qfh[kc][1] = *(const uint32_t*)&Qh[base + 8 * HD + k0];
            qfh[kc][2] = *(const uint32_t*)&Qh[base + k0 + 8];
            qfh[kc][3] = *(const uint32_t*)&Qh[base + 8 * HD + k0 + 8];
            qfl[kc][0] = *(const uint32_t*)&Ql[base + k0];
            qfl[kc][1] = *(const uint32_t*)&Ql[base + 8 * HD + k0];
            qfl[kc][2] = *(const uint32_t*)&Ql[base + k0 + 8];
            qfl[kc][3] = *(const uint32_t*)&Ql[base + 8 * HD + k0 + 8];
        }
    }

    float o[8][4];
#pragma unroll
    for (int nt = 0; nt < 8; nt++)
#pragma unroll
        for (int r = 0; r < 4; r++) o[nt][r] = 0.f;
    float m[2] = {-1e30f, -1e30f};
    float lsum[2] = {0.f, 0.f};

    const int t_hi = r0 >> 6;
    int jmin = r0 - (WIN - 1); if (jmin < 0) jmin = 0;
    const int t_lo = jmin >> 6;

    for (int t = t_hi; t >= t_lo; t--) {
        const int c0 = t * 64;
        __syncthreads();

#pragma unroll
        for (int i = 0; i < 4; i++) {
            int idx = i * 128 + tid;
            int row = idx >> 3, c8 = idx & 7;
            const size_t gofs = (size_t)(h * SEQ + c0 + row) * HD + c8 * 8;
            *(uint4*)&sKh[row * PITCH + c8 * 8] = *(const uint4*)&Kh[gofs];
            *(uint4*)&sKl[row * PITCH + c8 * 8] = *(const uint4*)&Kl[gofs];
        }
        {
            const int rp = tid & 31;
            const int cq = tid >> 5;
#pragma unroll
            for (int it = 0; it < 2; it++) {
                int c8 = cq + 4 * it;
                const size_t g0 = (size_t)(h * SEQ + c0 + 2 * rp) * HD + c8 * 8;
                uint4 h0 = *(const uint4*)&Vh[g0];
                uint4 h1 = *(const uint4*)&Vh[g0 + HD];
                uint4 l0 = *(const uint4*)&Vl[g0];
                uint4 l1 = *(const uint4*)&Vl[g0 + HD];
                const uint16_t* a0 = (const uint16_t*)&h0;
                const uint16_t* a1 = (const uint16_t*)&h1;
                const uint16_t* b0 = (const uint16_t*)&l0;
                const uint16_t* b1 = (const uint16_t*)&l1;
#pragma unroll
                for (int j = 0; j < 8; j++) {
                    int d = c8 * 8 + j;
                    *(uint32_t*)&sVh[d * PITCH + 2 * rp] =
                        (uint32_t)a0[j] | ((uint32_t)a1[j] << 16);
                    *(uint32_t*)&sVl[d * PITCH + 2 * rp] =
                        (uint32_t)b0[j] | ((uint32_t)b1[j] << 16);
                }
            }
        }
        __syncthreads();

        float s[8][4];
#pragma unroll
        for (int nt = 0; nt < 8; nt++)
#pragma unroll
            for (int r = 0; r < 4; r++) s[nt][r] = 0.f;

#pragma unroll
        for (int nt = 0; nt < 8; nt++) {
            const int nb = (nt * 8 + g) * PITCH;
#pragma unroll
            for (int kc = 0; kc < 4; kc++) {
                const int kk = kc * 16 + tg * 2;
                uint32_t bh[2], bl[2];
                bh[0] = *(uint32_t*)&sKh[nb + kk];
                bh[1] = *(uint32_t*)&sKh[nb + kk + 8];
                bl[0] = *(uint32_t*)&sKl[nb + kk];
                bl[1] = *(uint32_t*)&sKl[nb + kk + 8];
                MMA16816(s[nt], qfh[kc], bh);
                MMA16816(s[nt], qfh[kc], bl);
                MMA16816(s[nt], qfl[kc], bh);
            }
        }

        if (t == t_hi || t_hi - t >= 8) {
#pragma unroll
            for (int nt = 0; nt < 8; nt++)
#pragma unroll
                for (int r = 0; r < 4; r++) {
                    int row = qrow + (r >> 1) * 8;
                    int col = c0 + nt * 8 + tg * 2 + (r & 1);
                    if (col > row || row - col >= WIN) s[nt][r] = -1e30f;
                }
        }

        float p[8][4];
#pragma unroll
        for (int r2 = 0; r2 < 2; r2++) {
            float mx = -1e30f;
#pragma unroll
            for (int nt = 0; nt < 8; nt++)
                mx = fmaxf(mx, fmaxf(s[nt][r2 * 2], s[nt][r2 * 2 + 1]));
            mx = fmaxf(mx, __shfl_xor_sync(0xFFFFFFFFu, mx, 1));
            mx = fmaxf(mx, __shfl_xor_sync(0xFFFFFFFFu, mx, 2));
            float newm = fmaxf(m[r2], mx);
            float corr = __expf(m[r2] - newm);
            m[r2] = newm;
            float rs = 0.f;
#pragma unroll
            for (int nt = 0; nt < 8; nt++) {
                float p0 = __expf(s[nt][r2 * 2]     - newm);
                float p1 = __expf(s[nt][r2 * 2 + 1] - newm);
                p[nt][r2 * 2] = p0; p[nt][r2 * 2 + 1] = p1;
                rs += p0 + p1;
            }
            rs += __shfl_xor_sync(0xFFFFFFFFu, rs, 1);
            rs += __shfl_xor_sync(0xFFFFFFFFu, rs, 2);
            lsum[r2] = lsum[r2] * corr + rs;
#pragma unroll
            for (int nt = 0; nt < 8; nt++) {
                o[nt][r2 * 2]     *= corr;
                o[nt][r2 * 2 + 1] *= corr;
            }
        }

        uint32_t pah[4][4], pal[4][4];
#pragma unroll
        for (int kc = 0; kc < 4; kc++) {
#pragma unroll
            for (int r = 0; r < 2; r++) {
                float v0 = p[2 * kc][r * 2],     v1 = p[2 * kc][r * 2 + 1];
                float v2 = p[2 * kc + 1][r * 2], v3 = p[2 * kc + 1][r * 2 + 1];
                __nv_bfloat16 h0 = __float2bfloat16(v0), h1 = __float2bfloat16(v1);
                __nv_bfloat16 h2 = __float2bfloat16(v2), h3 = __float2bfloat16(v3);
                pah[kc][r]     = (uint32_t)*(uint16_t*)&h0 | ((uint32_t)*(uint16_t*)&h1 << 16);
                pah[kc][r + 2] = (uint32_t)*(uint16_t*)&h2 | ((uint32_t)*(uint16_t*)&h3 << 16);
                __nv_bfloat16 e0 = __float2bfloat16(v0 - __bfloat162float(h0));
                __nv_bfloat16 e1 = __float2bfloat16(v1 - __bfloat162float(h1));
                __nv_bfloat16 e2 = __float2bfloat16(v2 - __bfloat162float(h2));
                __nv_bfloat16 e3 = __float2bfloat16(v3 - __bfloat162float(h3));
                pal[kc][r]     = (uint32_t)*(uint16_t*)&e0 | ((uint32_t)*(uint16_t*)&e1 << 16);
                pal[kc][r + 2] = (uint32_t)*(uint16_t*)&e2 | ((uint32_t)*(uint16_t*)&e3 << 16);
            }
        }

#pragma unroll
        for (int nt = 0; nt < 8; nt++) {
            const int nb = (nt * 8 + g) * PITCH;
#pragma unroll
            for (int kc = 0; kc < 4; kc++) {
                const int kk = kc * 16 + tg * 2;
                uint32_t bh[2], bl[2];
                bh[0] = *(uint32_t*)&sVh[nb + kk];
                bh[1] = *(uint32_t*)&sVh[nb + kk + 8];
                bl[0] = *(uint32_t*)&sVl[nb + kk];
                bl[1] = *(uint32_t*)&sVl[nb + kk + 8];
                MMA16816(o[nt], pah[kc], bh);
                MMA16816(o[nt], pah[kc], bl);
                MMA16816(o[nt], pal[kc], bh);
            }
        }
    }

    const float inv0 = 1.0f / lsum[0];
    const float inv1 = 1.0f / lsum[1];
#pragma unroll
    for (int nt = 0; nt < 8; nt++) {
        const int col = h * HD + nt * 8 + tg * 2;
        split_store(Oh, Ol, (size_t)qrow * DM + col,
                    o[nt][0] * inv0, o[nt][1] * inv0);
        split_store(Oh, Ol, (size_t)(qrow + 8) * DM + col,
                    o[nt][2] * inv1, o[nt][3] * inv1);
    }
}

// ---------------------------------------------------------------------------
extern "C" void kernel_launch(void* const* d_in, const int* in_sizes, int n_in,
                              void* d_out, int out_size)
{
    const float* x     = (const float*)d_in[0];
    const float* w_qkv = (const float*)d_in[1];
    const float* w_out = (const float*)d_in[2];
    float* out = (float*)d_out;

    float* p_qkv;
    cudaGetSymbolAddress((void**)&p_qkv, g_qkv);
    __nv_bfloat16 *p_xh, *p_xl, *p_wqh, *p_wql, *p_woh, *p_wol, *p_atth, *p_attl;
    __nv_bfloat16 *p_qh, *p_ql, *p_kh, *p_kl, *p_vh, *p_vl;
    cudaGetSymbolAddress((void**)&p_xh,  g_xh);
    cudaGetSymbolAddress((void**)&p_xl,  g_xl);
    cudaGetSymbolAddress((void**)&p_wqh, g_wqh);
    cudaGetSymbolAddress((void**)&p_wql, g_wql);
    cudaGetSymbolAddress((void**)&p_woh, g_woh);
    cudaGetSymbolAddress((void**)&p_wol, g_wol);
    cudaGetSymbolAddress((void**)&p_atth, g_atth);
    cudaGetSymbolAddress((void**)&p_attl, g_attl);
    cudaGetSymbolAddress((void**)&p_qh, g_qh);
    cudaGetSymbolAddress((void**)&p_ql, g_ql);
    cudaGetSymbolAddress((void**)&p_kh, g_kh);
    cudaGetSymbolAddress((void**)&p_kl, g_kl);
    cudaGetSymbolAddress((void**)&p_vh, g_vh);
    cudaGetSymbolAddress((void**)&p_vl, g_vl);

    cudaFuncSetAttribute(gemm_bf16_kernel,
                         cudaFuncAttributeMaxDynamicSharedMemorySize, GEMM_SMEM);

    rope_table_kernel<<<(SEQ * 32 + 255) / 256, 256>>>();
    split_x_kernel<<<(SEQ * DM / 2 + 255) / 256, 256>>>(x);
    tsplit_kernel<<<dim3(3 * DM / 32, DM / 32), dim3(32, 8)>>>(w_qkv, p_wqh, p_wql, DM, 3 * DM);
    tsplit_kernel<<<dim3(DM / 32, DM / 32), dim3(32, 8)>>>(w_out, p_woh, p_wol, DM, DM);

    // 1) qkv = x @ w_qkv
    gemm_bf16_kernel<<<dim3(3 * DM / 64, SEQ / 128), 256, GEMM_SMEM>>>(
        p_xh, p_xl, p_wqh, p_wql, p_qkv, SEQ, 3 * DM, DM);

    // 2) RoPE + split scatter
    int total = SEQ * NH * 32;
    rope_scatter_kernel<<<(total + 255) / 256, 256>>>(p_qkv);

    // 3) HMMA flash attention (emits split-bf16 att)
    attn_mma_kernel<<<dim3(SEQ / 64, NH), 128>>>(p_qh, p_ql, p_kh, p_kl, p_vh, p_vl,
                                                 p_atth, p_attl);

    // 4) out = att @ w_out
    gemm_bf16_kernel<<<dim3(DM / 64, SEQ / 128), 256, GEMM_SMEM>>>(
        p_atth, p_attl, p_woh, p_wol, out, SEQ, DM, DM);
}